// round 5
// baseline (speedup 1.0000x reference)
#include <cuda_runtime.h>
#include <cuda_bf16.h>
#include <cstdint>

// ---------------------------------------------------------------------------
// Problem dims
// ---------------------------------------------------------------------------
static constexpr int BATCH = 16;
static constexpr int LQ    = 2048;
static constexpr int LK    = 2048;
static constexpr int DIM   = 128;
static constexpr float SCALE_LOG2E = 0.08838834764831845f * 1.4426950408889634f;

static constexpr int NPS = LK / 32;   // 64 partial sums per row
static constexpr size_t NEL  = (size_t)BATCH * LQ * DIM;   // Q/K/V elements
static constexpr size_t NELE = (size_t)BATCH * LQ * LK;    // E elements

__device__ float g_psums[(size_t)BATCH * LQ * NPS];
// bf16 hi/lo scratch (device globals: allowed scratch mechanism)
__device__ __nv_bfloat16 g_Qhi[NEL], g_Qlo[NEL];
__device__ __nv_bfloat16 g_Khi[NEL], g_Klo[NEL];
__device__ __nv_bfloat16 g_Vhi[NEL], g_Vlo[NEL];
__device__ __nv_bfloat16 g_Ehi[NELE], g_Elo[NELE];

// ---------------------------------------------------------------------------
// PTX helpers
// ---------------------------------------------------------------------------
__device__ __forceinline__ uint32_t smem_u32(const void* p) {
    uint32_t a;
    asm("{ .reg .u64 t; cvta.to.shared.u64 t, %1; cvt.u32.u64 %0, t; }" : "=r"(a) : "l"(p));
    return a;
}
__device__ __forceinline__ float ex2(float x) {
    float r; asm("ex2.approx.f32 %0, %1;" : "=f"(r) : "f"(x)); return r;
}
__device__ __forceinline__ void ldsm4(uint32_t (&r)[4], uint32_t addr) {
    asm volatile("ldmatrix.sync.aligned.m8n8.x4.shared.b16 {%0,%1,%2,%3}, [%4];"
                 : "=r"(r[0]), "=r"(r[1]), "=r"(r[2]), "=r"(r[3]) : "r"(addr));
}
__device__ __forceinline__ void ldsm4t(uint32_t (&r)[4], uint32_t addr) {
    asm volatile("ldmatrix.sync.aligned.m8n8.x4.trans.shared.b16 {%0,%1,%2,%3}, [%4];"
                 : "=r"(r[0]), "=r"(r[1]), "=r"(r[2]), "=r"(r[3]) : "r"(addr));
}
__device__ __forceinline__ void mma16816(float (&d)[4], const uint32_t (&a)[4],
                                         uint32_t b0, uint32_t b1) {
    asm volatile(
        "mma.sync.aligned.m16n8k16.row.col.f32.bf16.bf16.f32 "
        "{%0,%1,%2,%3},{%4,%5,%6,%7},{%8,%9},{%0,%1,%2,%3};"
        : "+f"(d[0]), "+f"(d[1]), "+f"(d[2]), "+f"(d[3])
        : "r"(a[0]), "r"(a[1]), "r"(a[2]), "r"(a[3]), "r"(b0), "r"(b1));
}
__device__ __forceinline__ void split4(float4 v, uint2& hi, uint2& lo) {
    __nv_bfloat16 h0 = __float2bfloat16_rn(v.x);
    __nv_bfloat16 h1 = __float2bfloat16_rn(v.y);
    __nv_bfloat16 h2 = __float2bfloat16_rn(v.z);
    __nv_bfloat16 h3 = __float2bfloat16_rn(v.w);
    __nv_bfloat16 l0 = __float2bfloat16_rn(v.x - __bfloat162float(h0));
    __nv_bfloat16 l1 = __float2bfloat16_rn(v.y - __bfloat162float(h1));
    __nv_bfloat16 l2 = __float2bfloat16_rn(v.z - __bfloat162float(h2));
    __nv_bfloat16 l3 = __float2bfloat16_rn(v.w - __bfloat162float(h3));
    __nv_bfloat162 a{h0, h1}, b{h2, h3}, c{l0, l1}, d{l2, l3};
    hi.x = *reinterpret_cast<uint32_t*>(&a); hi.y = *reinterpret_cast<uint32_t*>(&b);
    lo.x = *reinterpret_cast<uint32_t*>(&c); lo.y = *reinterpret_cast<uint32_t*>(&d);
}

// ---------------------------------------------------------------------------
// Kernel 0: preconvert Q (scaled), K, V -> bf16 hi/lo scratch
// grid: (NEL/4/256, 3)
// ---------------------------------------------------------------------------
__global__ __launch_bounds__(256) void preconvert_kernel(const float* __restrict__ Q,
                                                         const float* __restrict__ K,
                                                         const float* __restrict__ V) {
    const size_t t = (size_t)blockIdx.x * 256 + threadIdx.x;   // float4 index
    const int which = blockIdx.y;
    const float* src = (which == 0) ? Q : (which == 1) ? K : V;
    __nv_bfloat16* hi = (which == 0) ? g_Qhi : (which == 1) ? g_Khi : g_Vhi;
    __nv_bfloat16* lo = (which == 0) ? g_Qlo : (which == 1) ? g_Klo : g_Vlo;

    float4 v = reinterpret_cast<const float4*>(src)[t];
    if (which == 0) { v.x *= SCALE_LOG2E; v.y *= SCALE_LOG2E; v.z *= SCALE_LOG2E; v.w *= SCALE_LOG2E; }
    uint2 h, l; split4(v, h, l);
    reinterpret_cast<uint2*>(hi)[t] = h;
    reinterpret_cast<uint2*>(lo)[t] = l;
}

// ---------------------------------------------------------------------------
// QK kernel: 64(q) x 128(k), 8 warps (2m x 4n), warp tile 32x32, 2 CTAs/SM.
// Inputs already bf16 hi/lo. E = exp2(Qs·K^T) stored as bf16 hi/lo.
// ---------------------------------------------------------------------------
static constexpr int QK_RSB = 272;                 // 128 halves + 8 pad (bytes)
static constexpr int QK_QT  = 64  * QK_RSB;
static constexpr int QK_KT  = 128 * QK_RSB;
static constexpr int QK_QH = 0, QK_QL = QK_QT, QK_KH = 2 * QK_QT, QK_KL = 2 * QK_QT + QK_KT;
static constexpr int SM_QK = 2 * QK_QT + 2 * QK_KT;   // 104448

__global__ __launch_bounds__(256, 2) void qk_exp_kernel() {
    extern __shared__ char sm[];
    const uint32_t sb = smem_u32(sm);

    const int tid = threadIdx.x, lane = tid & 31, wid = tid >> 5;
    const int wm = wid >> 2, wn = wid & 3;
    const int b = blockIdx.z, qt = blockIdx.y * 64, kt = blockIdx.x * 128;

    const size_t qbase = ((size_t)b * LQ + qt) * DIM;
    const size_t kbase = ((size_t)b * LK + kt) * DIM;

    // Q tile: 64x128 halves, pure copies (hi + lo)
#pragma unroll
    for (int it = 0; it < 4; ++it) {
        int f = tid + it * 256;            // 0..1023 uint4
        int row = f >> 4, colu = (f & 15) * 8;
        int so = row * QK_RSB + colu * 2;
        size_t g = qbase + (size_t)row * DIM + colu;
        *reinterpret_cast<uint4*>(sm + QK_QH + so) = *reinterpret_cast<const uint4*>(g_Qhi + g);
        *reinterpret_cast<uint4*>(sm + QK_QL + so) = *reinterpret_cast<const uint4*>(g_Qlo + g);
    }
    // K tile: 128x128 halves
#pragma unroll
    for (int it = 0; it < 8; ++it) {
        int f = tid + it * 256;            // 0..2047 uint4
        int row = f >> 4, colu = (f & 15) * 8;
        int so = row * QK_RSB + colu * 2;
        size_t g = kbase + (size_t)row * DIM + colu;
        *reinterpret_cast<uint4*>(sm + QK_KH + so) = *reinterpret_cast<const uint4*>(g_Khi + g);
        *reinterpret_cast<uint4*>(sm + QK_KL + so) = *reinterpret_cast<const uint4*>(g_Klo + g);
    }
    __syncthreads();

    float acc[2][4][4];
#pragma unroll
    for (int mi = 0; mi < 2; ++mi)
#pragma unroll
        for (int ni = 0; ni < 4; ++ni)
#pragma unroll
            for (int c = 0; c < 4; ++c) acc[mi][ni][c] = 0.f;

    const uint32_t aoff = (uint32_t)((lane & 15) * QK_RSB + (lane >> 4) * 16);
    const uint32_t boff = (uint32_t)(((lane & 7) + (lane >> 4) * 8) * QK_RSB + ((lane >> 3) & 1) * 16);
    const uint32_t aHi = sb + QK_QH + (uint32_t)(wm * 32) * QK_RSB + aoff;
    const uint32_t aLo = sb + QK_QL + (uint32_t)(wm * 32) * QK_RSB + aoff;
    const uint32_t bHi = sb + QK_KH + (uint32_t)(wn * 32) * QK_RSB + boff;
    const uint32_t bLo = sb + QK_KL + (uint32_t)(wn * 32) * QK_RSB + boff;

#pragma unroll
    for (int pass = 0; pass < 3; ++pass) {
        const uint32_t ab = (pass == 2) ? aLo : aHi;
        const uint32_t bb = (pass == 1) ? bLo : bHi;
#pragma unroll
        for (int ks = 0; ks < 8; ++ks) {
            uint32_t a[2][4];
#pragma unroll
            for (int mi = 0; mi < 2; ++mi) ldsm4(a[mi], ab + (uint32_t)(mi * 16) * QK_RSB + ks * 32);
            uint32_t bf[2][4];
#pragma unroll
            for (int np = 0; np < 2; ++np) ldsm4(bf[np], bb + (uint32_t)(np * 16) * QK_RSB + ks * 32);
#pragma unroll
            for (int mi = 0; mi < 2; ++mi)
#pragma unroll
                for (int ni = 0; ni < 4; ++ni)
                    mma16816(acc[mi][ni], a[mi], bf[ni >> 1][(ni & 1) * 2], bf[ni >> 1][(ni & 1) * 2 + 1]);
        }
    }

    // epilogue: exp2 -> bf16 hi/lo E + deterministic partial sums
    const int r0 = qt + wm * 32 + (lane >> 2);
    const int c0 = kt + wn * 32 + (lane & 3) * 2;
    const int pc = blockIdx.x * 4 + wn;

#pragma unroll
    for (int mi = 0; mi < 2; ++mi) {
        float s0 = 0.f, s1 = 0.f;
        const int rr = r0 + mi * 16;
        const size_t e0base = ((size_t)b * LQ + rr)     * LK + c0;
        const size_t e1base = ((size_t)b * LQ + rr + 8) * LK + c0;
#pragma unroll
        for (int ni = 0; ni < 4; ++ni) {
            float e0 = ex2(acc[mi][ni][0]);
            float e1 = ex2(acc[mi][ni][1]);
            float e2 = ex2(acc[mi][ni][2]);
            float e3 = ex2(acc[mi][ni][3]);
            s0 += e0 + e1; s1 += e2 + e3;
            __nv_bfloat16 h0 = __float2bfloat16_rn(e0), h1 = __float2bfloat16_rn(e1);
            __nv_bfloat16 h2 = __float2bfloat16_rn(e2), h3 = __float2bfloat16_rn(e3);
            __nv_bfloat162 hp0{h0, h1}, hp1{h2, h3};
            __nv_bfloat162 lp0{__float2bfloat16_rn(e0 - __bfloat162float(h0)),
                               __float2bfloat16_rn(e1 - __bfloat162float(h1))};
            __nv_bfloat162 lp1{__float2bfloat16_rn(e2 - __bfloat162float(h2)),
                               __float2bfloat16_rn(e3 - __bfloat162float(h3))};
            *reinterpret_cast<uint32_t*>(g_Ehi + e0base + ni * 8) = *reinterpret_cast<uint32_t*>(&hp0);
            *reinterpret_cast<uint32_t*>(g_Elo + e0base + ni * 8) = *reinterpret_cast<uint32_t*>(&lp0);
            *reinterpret_cast<uint32_t*>(g_Ehi + e1base + ni * 8) = *reinterpret_cast<uint32_t*>(&hp1);
            *reinterpret_cast<uint32_t*>(g_Elo + e1base + ni * 8) = *reinterpret_cast<uint32_t*>(&lp1);
        }
        s0 += __shfl_xor_sync(0xFFFFFFFFu, s0, 1);
        s0 += __shfl_xor_sync(0xFFFFFFFFu, s0, 2);
        s1 += __shfl_xor_sync(0xFFFFFFFFu, s1, 1);
        s1 += __shfl_xor_sync(0xFFFFFFFFu, s1, 2);
        if ((lane & 3) == 0) {
            g_psums[((size_t)b * LQ + rr)     * NPS + pc] = s0;
            g_psums[((size_t)b * LQ + rr + 8) * NPS + pc] = s1;
        }
    }
}

// ---------------------------------------------------------------------------
// PV kernel: 64(q) x 128(d), K in 32 chunks of 64, double-buffered smem +
// register prefetch. A = unnormalized E (bf16); R scaled by inv in epilogue.
// P (fp32, normalized) written during the A-copy. 2 CTAs/SM.
// ---------------------------------------------------------------------------
static constexpr int PV_ARS = 144;                 // 64 halves + 8 pad (bytes)
static constexpr int PV_BRS = 272;
static constexpr int PV_AT  = 64 * PV_ARS;         // 9216
static constexpr int PV_BT  = 64 * PV_BRS;         // 17408
static constexpr int PV_AH = 0, PV_AL = PV_AT, PV_BH = 2 * PV_AT, PV_BL = 2 * PV_AT + PV_BT;
static constexpr int PV_STAGE = 2 * PV_AT + 2 * PV_BT;   // 53248
static constexpr int PV_INV = 2 * PV_STAGE;
static constexpr int SM_PV  = PV_INV + 256;

__global__ __launch_bounds__(256, 2) void pv_kernel(float* __restrict__ P,
                                                    float* __restrict__ R) {
    extern __shared__ char sm[];
    const uint32_t sb = smem_u32(sm);

    const int tid = threadIdx.x, lane = tid & 31, wid = tid >> 5;
    const int wm = wid >> 2, wn = wid & 3;
    const int qt = blockIdx.x * 64, b = blockIdx.y;

    float* inv = reinterpret_cast<float*>(sm + PV_INV);
    if (tid < 64) {
        const float* ps = &g_psums[((size_t)b * LQ + qt + tid) * NPS];
        float s = 0.f;
#pragma unroll
        for (int j = 0; j < NPS; ++j) s += ps[j];
        inv[tid] = 1.f / s;
    }
    __syncthreads();

    const size_t ebase = ((size_t)b * LQ + qt) * LK;
    const size_t vbase = (size_t)b * LK * DIM;
    float* Pb = P + ebase;

    float acc[2][4][4];
#pragma unroll
    for (int mi = 0; mi < 2; ++mi)
#pragma unroll
        for (int ni = 0; ni < 4; ++ni)
#pragma unroll
            for (int c = 0; c < 4; ++c) acc[mi][ni][c] = 0.f;

    const uint32_t aoff  = (uint32_t)((lane & 15) * PV_ARS + (lane >> 4) * 16);
    const uint32_t boffT = (uint32_t)(((lane & 7) + ((lane >> 3) & 1) * 8) * PV_BRS + (lane >> 4) * 16);

    uint4 ah[2], al[2], vh[4], vl[4];
    // prologue: chunk 0
#pragma unroll
    for (int it = 0; it < 2; ++it) {
        int f = tid + it * 256, row = f >> 3, colu = (f & 7) * 8;
        size_t g = ebase + (size_t)row * LK + colu;
        ah[it] = *reinterpret_cast<const uint4*>(g_Ehi + g);
        al[it] = *reinterpret_cast<const uint4*>(g_Elo + g);
    }
#pragma unroll
    for (int it = 0; it < 4; ++it) {
        int f = tid + it * 256, row = f >> 4, colu = (f & 15) * 8;
        size_t g = vbase + (size_t)row * DIM + colu;
        vh[it] = *reinterpret_cast<const uint4*>(g_Vhi + g);
        vl[it] = *reinterpret_cast<const uint4*>(g_Vlo + g);
    }

    for (int kc = 0; kc < 32; ++kc) {
        const int st = (kc & 1) * PV_STAGE;
        // stage A + write normalized P
#pragma unroll
        for (int it = 0; it < 2; ++it) {
            int f = tid + it * 256, row = f >> 3, colu = (f & 7) * 8;
            int so = st + row * PV_ARS + colu * 2;
            *reinterpret_cast<uint4*>(sm + PV_AH + so) = ah[it];
            *reinterpret_cast<uint4*>(sm + PV_AL + so) = al[it];
            const float iv = inv[row];
            const __nv_bfloat162* hp = reinterpret_cast<const __nv_bfloat162*>(&ah[it]);
            const __nv_bfloat162* lp = reinterpret_cast<const __nv_bfloat162*>(&al[it]);
            float* pd = Pb + (size_t)row * LK + kc * 64 + colu;
            float4 o0, o1;
            {
                float2 h0 = __bfloat1622float2(hp[0]), l0 = __bfloat1622float2(lp[0]);
                float2 h1 = __bfloat1622float2(hp[1]), l1 = __bfloat1622float2(lp[1]);
                o0.x = (h0.x + l0.x) * iv; o0.y = (h0.y + l0.y) * iv;
                o0.z = (h1.x + l1.x) * iv; o0.w = (h1.y + l1.y) * iv;
                float2 h2 = __bfloat1622float2(hp[2]), l2 = __bfloat1622float2(lp[2]);
                float2 h3 = __bfloat1622float2(hp[3]), l3 = __bfloat1622float2(lp[3]);
                o1.x = (h2.x + l2.x) * iv; o1.y = (h2.y + l2.y) * iv;
                o1.z = (h3.x + l3.x) * iv; o1.w = (h3.y + l3.y) * iv;
            }
            *reinterpret_cast<float4*>(pd)     = o0;
            *reinterpret_cast<float4*>(pd + 4) = o1;
        }
        // stage V (pure copies)
#pragma unroll
        for (int it = 0; it < 4; ++it) {
            int f = tid + it * 256, row = f >> 4, colu = (f & 15) * 8;
            int so = st + row * PV_BRS + colu * 2;
            *reinterpret_cast<uint4*>(sm + PV_BH + so) = vh[it];
            *reinterpret_cast<uint4*>(sm + PV_BL + so) = vl[it];
        }
        __syncthreads();

        // prefetch next chunk
        if (kc < 31) {
#pragma unroll
            for (int it = 0; it < 2; ++it) {
                int f = tid + it * 256, row = f >> 3, colu = (f & 7) * 8;
                size_t g = ebase + (size_t)row * LK + (kc + 1) * 64 + colu;
                ah[it] = *reinterpret_cast<const uint4*>(g_Ehi + g);
                al[it] = *reinterpret_cast<const uint4*>(g_Elo + g);
            }
#pragma unroll
            for (int it = 0; it < 4; ++it) {
                int f = tid + it * 256, row = f >> 4, colu = (f & 15) * 8;
                size_t g = vbase + (size_t)((kc + 1) * 64 + row) * DIM + colu;
                vh[it] = *reinterpret_cast<const uint4*>(g_Vhi + g);
                vl[it] = *reinterpret_cast<const uint4*>(g_Vlo + g);
            }
        }

        const uint32_t aHi = sb + PV_AH + st + (uint32_t)(wm * 32) * PV_ARS + aoff;
        const uint32_t aLo = sb + PV_AL + st + (uint32_t)(wm * 32) * PV_ARS + aoff;
        const uint32_t bHi = sb + PV_BH + st + boffT + (uint32_t)(wn * 32) * 2;
        const uint32_t bLo = sb + PV_BL + st + boffT + (uint32_t)(wn * 32) * 2;

#pragma unroll
        for (int pass = 0; pass < 3; ++pass) {
            const uint32_t ab = (pass == 2) ? aLo : aHi;
            const uint32_t bb = (pass == 1) ? bLo : bHi;
#pragma unroll
            for (int ks = 0; ks < 4; ++ks) {
                uint32_t a[2][4];
#pragma unroll
                for (int mi = 0; mi < 2; ++mi) ldsm4(a[mi], ab + (uint32_t)(mi * 16) * PV_ARS + ks * 32);
                uint32_t bf[2][4];
#pragma unroll
                for (int np = 0; np < 2; ++np) ldsm4t(bf[np], bb + (uint32_t)(ks * 16) * PV_BRS + np * 32);
#pragma unroll
                for (int mi = 0; mi < 2; ++mi)
#pragma unroll
                    for (int ni = 0; ni < 4; ++ni)
                        mma16816(acc[mi][ni], a[mi], bf[ni >> 1][(ni & 1) * 2], bf[ni >> 1][(ni & 1) * 2 + 1]);
            }
        }
    }

    // epilogue: scale by inv, store R
    const int r0 = qt + wm * 32 + (lane >> 2);
    const int c0 = wn * 32 + (lane & 3) * 2;
#pragma unroll
    for (int mi = 0; mi < 2; ++mi) {
        const int rr = r0 + mi * 16;
        const float iv0 = inv[rr - qt], iv1 = inv[rr + 8 - qt];
#pragma unroll
        for (int ni = 0; ni < 4; ++ni) {
            float2 lo2{acc[mi][ni][0] * iv0, acc[mi][ni][1] * iv0};
            float2 hi2{acc[mi][ni][2] * iv1, acc[mi][ni][3] * iv1};
            *reinterpret_cast<float2*>(R + ((size_t)b * LQ + rr)     * DIM + c0 + ni * 8) = lo2;
            *reinterpret_cast<float2*>(R + ((size_t)b * LQ + rr + 8) * DIM + c0 + ni * 8) = hi2;
        }
    }
}

// ---------------------------------------------------------------------------
// Launch: d_out = [ R | P ]
// ---------------------------------------------------------------------------
extern "C" void kernel_launch(void* const* d_in, const int* in_sizes, int n_in,
                              void* d_out, int out_size) {
    const float* Q = (const float*)d_in[0];
    const float* K = (const float*)d_in[1];
    const float* V = (const float*)d_in[2];
    float* R = (float*)d_out;
    float* P = (float*)d_out + (size_t)BATCH * LQ * DIM;

    cudaFuncSetAttribute(qk_exp_kernel, cudaFuncAttributeMaxDynamicSharedMemorySize, SM_QK);
    cudaFuncSetAttribute(pv_kernel,     cudaFuncAttributeMaxDynamicSharedMemorySize, SM_PV);

    {
        dim3 grid((unsigned)(NEL / 4 / 256), 3);
        preconvert_kernel<<<grid, 256>>>(Q, K, V);
    }
    {
        dim3 grid(LK / 128, LQ / 64, BATCH);
        qk_exp_kernel<<<grid, 256, SM_QK>>>();
    }
    {
        dim3 grid(LQ / 64, BATCH);
        pv_kernel<<<grid, 256, SM_PV>>>(P, R);
    }
}

// round 6
// speedup vs baseline: 1.2011x; 1.2011x over previous
#include <cuda_runtime.h>
#include <cuda_fp16.h>
#include <cstdint>

// ---------------------------------------------------------------------------
// Problem dims
// ---------------------------------------------------------------------------
static constexpr int BATCH = 16;
static constexpr int LQ    = 2048;
static constexpr int LK    = 2048;
static constexpr int DIM   = 128;
static constexpr float SCALE_LOG2E = 0.08838834764831845f * 1.4426950408889634f;

static constexpr size_t NEL = (size_t)BATCH * LQ * DIM;

// fp16 scratch (device globals = allowed scratch)
__device__ __half g_Qhi[NEL], g_Qlo[NEL];
__device__ __half g_Khi[NEL], g_Klo[NEL];
__device__ __half g_Vhi[NEL];

// ---------------------------------------------------------------------------
// PTX helpers (sm_80-class only: ldmatrix, mma.sync f16, cp.async, ex2)
// ---------------------------------------------------------------------------
__device__ __forceinline__ uint32_t smem_u32(const void* p) {
    uint32_t a;
    asm("{ .reg .u64 t; cvta.to.shared.u64 t, %1; cvt.u32.u64 %0, t; }" : "=r"(a) : "l"(p));
    return a;
}
__device__ __forceinline__ float ex2(float x) {
    float r; asm("ex2.approx.f32 %0, %1;" : "=f"(r) : "f"(x)); return r;
}
__device__ __forceinline__ void ldsm4(uint32_t (&r)[4], uint32_t addr) {
    asm volatile("ldmatrix.sync.aligned.m8n8.x4.shared.b16 {%0,%1,%2,%3}, [%4];"
                 : "=r"(r[0]), "=r"(r[1]), "=r"(r[2]), "=r"(r[3]) : "r"(addr));
}
__device__ __forceinline__ void ldsm4t(uint32_t (&r)[4], uint32_t addr) {
    asm volatile("ldmatrix.sync.aligned.m8n8.x4.trans.shared.b16 {%0,%1,%2,%3}, [%4];"
                 : "=r"(r[0]), "=r"(r[1]), "=r"(r[2]), "=r"(r[3]) : "r"(addr));
}
__device__ __forceinline__ void mma16816(float (&d)[4], const uint32_t (&a)[4],
                                         uint32_t b0, uint32_t b1) {
    asm volatile(
        "mma.sync.aligned.m16n8k16.row.col.f32.f16.f16.f32 "
        "{%0,%1,%2,%3},{%4,%5,%6,%7},{%8,%9},{%0,%1,%2,%3};"
        : "+f"(d[0]), "+f"(d[1]), "+f"(d[2]), "+f"(d[3])
        : "r"(a[0]), "r"(a[1]), "r"(a[2]), "r"(a[3]), "r"(b0), "r"(b1));
}
__device__ __forceinline__ void cp16(uint32_t smem, const void* g) {
    asm volatile("cp.async.cg.shared.global [%0], [%1], 16;" :: "r"(smem), "l"(g) : "memory");
}
__device__ __forceinline__ void cp_commit() { asm volatile("cp.async.commit_group;" ::: "memory"); }
__device__ __forceinline__ void cp_wait0()  { asm volatile("cp.async.wait_group 0;" ::: "memory"); }

__device__ __forceinline__ uint32_t packh2(__half a, __half b) {
    __half2 p{a, b};
    return *reinterpret_cast<uint32_t*>(&p);
}

// ---------------------------------------------------------------------------
// Kernel 0: preconvert Q (scaled by SCALE*log2e, hi/lo), K (hi/lo), V (hi)
// ---------------------------------------------------------------------------
__global__ __launch_bounds__(256) void preconvert_kernel(const float* __restrict__ Q,
                                                         const float* __restrict__ K,
                                                         const float* __restrict__ V) {
    const size_t t = (size_t)blockIdx.x * 256 + threadIdx.x;   // float4 index
    const int which = blockIdx.y;
    const float* src = (which == 0) ? Q : (which == 1) ? K : V;
    float4 v = reinterpret_cast<const float4*>(src)[t];
    if (which == 0) { v.x *= SCALE_LOG2E; v.y *= SCALE_LOG2E; v.z *= SCALE_LOG2E; v.w *= SCALE_LOG2E; }

    __half h0 = __float2half_rn(v.x), h1 = __float2half_rn(v.y);
    __half h2 = __float2half_rn(v.z), h3 = __float2half_rn(v.w);
    uint2 hh{packh2(h0, h1), packh2(h2, h3)};

    if (which == 2) {
        reinterpret_cast<uint2*>(g_Vhi)[t] = hh;
        return;
    }
    __half l0 = __float2half_rn(v.x - __half2float(h0));
    __half l1 = __float2half_rn(v.y - __half2float(h1));
    __half l2 = __float2half_rn(v.z - __half2float(h2));
    __half l3 = __float2half_rn(v.w - __half2float(h3));
    uint2 ll{packh2(l0, l1), packh2(l2, l3)};
    if (which == 0) {
        reinterpret_cast<uint2*>(g_Qhi)[t] = hh;
        reinterpret_cast<uint2*>(g_Qlo)[t] = ll;
    } else {
        reinterpret_cast<uint2*>(g_Khi)[t] = hh;
        reinterpret_cast<uint2*>(g_Klo)[t] = ll;
    }
}

// ---------------------------------------------------------------------------
// Fused attention kernel.
// CTA: 64 q-rows x full LK, 4 warps (m16 each), 128 threads.
// Per 32-wide k-chunk: S = Qhi*Khi + Qlo*Khi + Qhi*Klo (f32 acc, tcgen-free),
// e = exp2(S) -> store to P region (unnormalized), convert e -> fp16 hi/lo
// A-fragments in registers, R += (Shi+Slo)*Vhi.  Tail: scale R by 1/rowsum,
// normalize P rows in place.
// ---------------------------------------------------------------------------
static constexpr int RSB   = 272;                 // padded row stride (bytes)
static constexpr int KSZ   = 32 * RSB;            // 8704: one 32x128 half tile
static constexpr int OFF_KHI = 0, OFF_KLO = KSZ, OFF_VHI = 2 * KSZ;
static constexpr int STAGE = 3 * KSZ;             // 26112
static constexpr int INVOFF = 2 * STAGE;          // 52224
static constexpr int SMEM_BYTES = INVOFF + 256;   // 52480
// Q staging (pre-loop, reuses buffer area): hi at 0, lo at 64*272=17408

__global__ __launch_bounds__(128) void fused_attn_kernel(float* __restrict__ P,
                                                         float* __restrict__ R) {
    extern __shared__ char sm[];
    const uint32_t sb = smem_u32(sm);

    const int tid = threadIdx.x, lane = tid & 31, w = tid >> 5;
    const int g = lane >> 2, c2 = (lane & 3) * 2;
    const int qt = blockIdx.x * 64, b = blockIdx.y;

    const size_t qbase = ((size_t)b * LQ + qt) * DIM;

    // ---- stage Q (hi/lo) into smem via cp.async ----
#pragma unroll
    for (int j = 0; j < 8; ++j) {
        int i = tid + j * 128;             // 0..1023
        int row = i >> 4, chk = i & 15;
        uint32_t so = (uint32_t)(row * RSB + chk * 16);
        const size_t gg = qbase + (size_t)row * DIM + chk * 8;
        cp16(sb + so,         g_Qhi + gg);
        cp16(sb + 17408 + so, g_Qlo + gg);
    }
    cp_commit(); cp_wait0();
    __syncthreads();

    // ---- load Q A-fragments into registers (8 kfrags x 4 regs, hi+lo) ----
    const uint32_t aoff = (uint32_t)((lane & 15) * RSB + (lane >> 4) * 16);
    uint32_t qh[8][4], ql[8][4];
    {
        const uint32_t qa = sb + (uint32_t)(w * 16) * RSB + aoff;
#pragma unroll
        for (int ks = 0; ks < 8; ++ks) {
            ldsm4(qh[ks], qa + ks * 32);
            ldsm4(ql[ks], qa + 17408 + ks * 32);
        }
    }
    __syncthreads();   // Q region now reusable as chunk buffers

    // B-operand lane offsets (proven layouts from prior rounds)
    const uint32_t boff  = (uint32_t)(((lane & 7) + (lane >> 4) * 8) * RSB + ((lane >> 3) & 1) * 16);
    const uint32_t boffT = (uint32_t)(((lane & 7) + ((lane >> 3) & 1) * 8) * RSB + (lane >> 4) * 16);

    // ---- stage chunk 0 ----
    {
        const size_t kb = ((size_t)b * LK + 0) * DIM;
#pragma unroll
        for (int j = 0; j < 4; ++j) {
            int i = tid + j * 128;
            int row = i >> 4, chk = i & 15;
            uint32_t so = (uint32_t)(row * RSB + chk * 16);
            const size_t gg = kb + (size_t)row * DIM + chk * 8;
            cp16(sb + OFF_KHI + so, g_Khi + gg);
            cp16(sb + OFF_KLO + so, g_Klo + gg);
            cp16(sb + OFF_VHI + so, g_Vhi + gg);
        }
        cp_commit(); cp_wait0();
    }
    __syncthreads();

    float racc[16][4];
#pragma unroll
    for (int j = 0; j < 16; ++j)
#pragma unroll
        for (int c = 0; c < 4; ++c) racc[j][c] = 0.f;
    float rs0 = 0.f, rs1 = 0.f;

    // E row pointers for this thread
    float* Er0 = P + ((size_t)b * LQ + qt + w * 16 + g) * LK + c2;
    float* Er1 = Er0 + (size_t)8 * LK;

#pragma unroll 1
    for (int kc = 0; kc < 64; ++kc) {
        // stage next chunk
        if (kc < 63) {
            const uint32_t dst = sb + (uint32_t)(((kc + 1) & 1) * STAGE);
            const size_t kb = ((size_t)b * LK + (kc + 1) * 32) * DIM;
#pragma unroll
            for (int j = 0; j < 4; ++j) {
                int i = tid + j * 128;
                int row = i >> 4, chk = i & 15;
                uint32_t so = (uint32_t)(row * RSB + chk * 16);
                const size_t gg = kb + (size_t)row * DIM + chk * 8;
                cp16(dst + OFF_KHI + so, g_Khi + gg);
                cp16(dst + OFF_KLO + so, g_Klo + gg);
                cp16(dst + OFF_VHI + so, g_Vhi + gg);
            }
            cp_commit();
        }

        const uint32_t buf = sb + (uint32_t)((kc & 1) * STAGE);

        // ---- QK: S (64x32 per CTA; m16n32 per warp), 3 products ----
        float s[4][4];
#pragma unroll
        for (int j = 0; j < 4; ++j)
#pragma unroll
            for (int c = 0; c < 4; ++c) s[j][c] = 0.f;

        const uint32_t kh = buf + OFF_KHI + boff;
        const uint32_t kl = buf + OFF_KLO + boff;
#pragma unroll
        for (int ks = 0; ks < 8; ++ks) {
            uint32_t bh[2][4], bl[2][4];
            ldsm4(bh[0], kh + ks * 32);
            ldsm4(bh[1], kh + 16 * RSB + ks * 32);
            ldsm4(bl[0], kl + ks * 32);
            ldsm4(bl[1], kl + 16 * RSB + ks * 32);
#pragma unroll
            for (int np = 0; np < 2; ++np)
#pragma unroll
                for (int nb = 0; nb < 2; ++nb) {
                    const int j = np * 2 + nb;
                    mma16816(s[j], qh[ks], bh[np][nb * 2], bh[np][nb * 2 + 1]);
                    mma16816(s[j], ql[ks], bh[np][nb * 2], bh[np][nb * 2 + 1]);
                    mma16816(s[j], qh[ks], bl[np][nb * 2], bl[np][nb * 2 + 1]);
                }
        }

        // ---- exp2, store unnormalized E, rowsums, pack fp16 hi/lo A-frags ----
        float e[4][4];
#pragma unroll
        for (int j = 0; j < 4; ++j) {
            e[j][0] = ex2(s[j][0]); e[j][1] = ex2(s[j][1]);
            e[j][2] = ex2(s[j][2]); e[j][3] = ex2(s[j][3]);
            rs0 += e[j][0] + e[j][1];
            rs1 += e[j][2] + e[j][3];
            float2 v0{e[j][0], e[j][1]}, v1{e[j][2], e[j][3]};
            *reinterpret_cast<float2*>(Er0 + kc * 32 + j * 8) = v0;
            *reinterpret_cast<float2*>(Er1 + kc * 32 + j * 8) = v1;
        }
        uint32_t sh[2][4], sl[2][4];
#pragma unroll
        for (int kf = 0; kf < 2; ++kf)
#pragma unroll
            for (int jj = 0; jj < 2; ++jj) {
                const int j = kf * 2 + jj;
                __half h0 = __float2half_rn(e[j][0]), h1 = __float2half_rn(e[j][1]);
                __half h2 = __float2half_rn(e[j][2]), h3 = __float2half_rn(e[j][3]);
                sh[kf][jj * 2 + 0] = packh2(h0, h1);
                sh[kf][jj * 2 + 1] = packh2(h2, h3);
                sl[kf][jj * 2 + 0] = packh2(__float2half_rn(e[j][0] - __half2float(h0)),
                                            __float2half_rn(e[j][1] - __half2float(h1)));
                sl[kf][jj * 2 + 1] = packh2(__float2half_rn(e[j][2] - __half2float(h2)),
                                            __float2half_rn(e[j][3] - __half2float(h3)));
            }

        // ---- PV: R += (Shi + Slo) * Vhi ----
        const uint32_t vb = buf + OFF_VHI + boffT;
#pragma unroll
        for (int kf = 0; kf < 2; ++kf)
#pragma unroll
            for (int nb = 0; nb < 8; ++nb) {
                uint32_t bv[4];
                ldsm4t(bv, vb + (uint32_t)(kf * 16) * RSB + nb * 32);
                mma16816(racc[nb * 2],     sh[kf], bv[0], bv[1]);
                mma16816(racc[nb * 2],     sl[kf], bv[0], bv[1]);
                mma16816(racc[nb * 2 + 1], sh[kf], bv[2], bv[3]);
                mma16816(racc[nb * 2 + 1], sl[kf], bv[2], bv[3]);
            }

        cp_wait0();
        __syncthreads();
    }

    // ---- rowsums -> inverses ----
    rs0 += __shfl_xor_sync(0xFFFFFFFFu, rs0, 1);
    rs0 += __shfl_xor_sync(0xFFFFFFFFu, rs0, 2);
    rs1 += __shfl_xor_sync(0xFFFFFFFFu, rs1, 1);
    rs1 += __shfl_xor_sync(0xFFFFFFFFu, rs1, 2);
    const float iv0 = 1.f / rs0, iv1 = 1.f / rs1;

    float* invsm = reinterpret_cast<float*>(sm + INVOFF);
    if ((lane & 3) == 0) {
        invsm[w * 16 + g]     = iv0;
        invsm[w * 16 + 8 + g] = iv1;
    }

    // ---- store R (scaled by row inverse) ----
    {
        float* Rp = R + ((size_t)b * LQ + qt + w * 16 + g) * DIM + c2;
#pragma unroll
        for (int j = 0; j < 16; ++j) {
            float2 v0{racc[j][0] * iv0, racc[j][1] * iv0};
            float2 v1{racc[j][2] * iv1, racc[j][3] * iv1};
            *reinterpret_cast<float2*>(Rp + j * 8)             = v0;
            *reinterpret_cast<float2*>(Rp + 8 * DIM + j * 8)   = v1;
        }
    }

    __syncthreads();   // invsm visible; all E writes of this CTA done

    // ---- normalize P rows in place ----
    float* Pt = P + ((size_t)b * LQ + qt) * LK;
#pragma unroll 4
    for (int it = 0; it < 256; ++it) {
        int idx = tid + it * 128;          // 0..32767 float4 slots
        int r = idx >> 9, c4 = idx & 511;
        float4* p = reinterpret_cast<float4*>(Pt + (size_t)r * LK) + c4;
        float4 v = *p;
        const float iv = invsm[r];
        v.x *= iv; v.y *= iv; v.z *= iv; v.w *= iv;
        *p = v;
    }
}

// ---------------------------------------------------------------------------
// Launch: d_out = [ R | P ]
// ---------------------------------------------------------------------------
extern "C" void kernel_launch(void* const* d_in, const int* in_sizes, int n_in,
                              void* d_out, int out_size) {
    const float* Q = (const float*)d_in[0];
    const float* K = (const float*)d_in[1];
    const float* V = (const float*)d_in[2];
    float* R = (float*)d_out;
    float* P = (float*)d_out + (size_t)BATCH * LQ * DIM;

    cudaFuncSetAttribute(fused_attn_kernel, cudaFuncAttributeMaxDynamicSharedMemorySize, SMEM_BYTES);

    {
        dim3 grid((unsigned)(NEL / 4 / 256), 3);
        preconvert_kernel<<<grid, 256>>>(Q, K, V);
    }
    {
        dim3 grid(LQ / 64, BATCH);
        fused_attn_kernel<<<grid, 128, SMEM_BYTES>>>(P, R);
    }
}

// round 7
// speedup vs baseline: 1.5881x; 1.3222x over previous
#include <cuda_runtime.h>
#include <cuda_fp16.h>
#include <cstdint>

// ---------------------------------------------------------------------------
// Problem dims
// ---------------------------------------------------------------------------
static constexpr int BATCH = 16;
static constexpr int LQ    = 2048;
static constexpr int LK    = 2048;
static constexpr int DIM   = 128;
static constexpr float SCALE_LOG2E = 0.08838834764831845f * 1.4426950408889634f;

static constexpr size_t NEL = (size_t)BATCH * LQ * DIM;

// fp16 scratch (device globals = allowed scratch)
__device__ __half g_Qhi[NEL], g_Qlo[NEL];
__device__ __half g_Khi[NEL], g_Klo[NEL];
__device__ __half g_Vhi[NEL];

// ---------------------------------------------------------------------------
// PTX helpers (sm_80-class only)
// ---------------------------------------------------------------------------
__device__ __forceinline__ uint32_t smem_u32(const void* p) {
    uint32_t a;
    asm("{ .reg .u64 t; cvta.to.shared.u64 t, %1; cvt.u32.u64 %0, t; }" : "=r"(a) : "l"(p));
    return a;
}
__device__ __forceinline__ float ex2(float x) {
    float r; asm("ex2.approx.f32 %0, %1;" : "=f"(r) : "f"(x)); return r;
}
__device__ __forceinline__ void ldsm4(uint32_t (&r)[4], uint32_t addr) {
    asm volatile("ldmatrix.sync.aligned.m8n8.x4.shared.b16 {%0,%1,%2,%3}, [%4];"
                 : "=r"(r[0]), "=r"(r[1]), "=r"(r[2]), "=r"(r[3]) : "r"(addr));
}
__device__ __forceinline__ void ldsm4t(uint32_t (&r)[4], uint32_t addr) {
    asm volatile("ldmatrix.sync.aligned.m8n8.x4.trans.shared.b16 {%0,%1,%2,%3}, [%4];"
                 : "=r"(r[0]), "=r"(r[1]), "=r"(r[2]), "=r"(r[3]) : "r"(addr));
}
__device__ __forceinline__ void mma16816(float (&d)[4], const uint32_t (&a)[4],
                                         uint32_t b0, uint32_t b1) {
    asm volatile(
        "mma.sync.aligned.m16n8k16.row.col.f32.f16.f16.f32 "
        "{%0,%1,%2,%3},{%4,%5,%6,%7},{%8,%9},{%0,%1,%2,%3};"
        : "+f"(d[0]), "+f"(d[1]), "+f"(d[2]), "+f"(d[3])
        : "r"(a[0]), "r"(a[1]), "r"(a[2]), "r"(a[3]), "r"(b0), "r"(b1));
}
__device__ __forceinline__ void cp16(uint32_t smem, const void* g) {
    asm volatile("cp.async.cg.shared.global [%0], [%1], 16;" :: "r"(smem), "l"(g) : "memory");
}
__device__ __forceinline__ void cp_commit() { asm volatile("cp.async.commit_group;" ::: "memory"); }
__device__ __forceinline__ void cp_wait0()  { asm volatile("cp.async.wait_group 0;" ::: "memory"); }

__device__ __forceinline__ uint32_t packh2(__half a, __half b) {
    __half2 p{a, b};
    return *reinterpret_cast<uint32_t*>(&p);
}

// ---------------------------------------------------------------------------
// Kernel 0: preconvert Q (scaled, hi/lo), K (hi/lo), V (hi)
// ---------------------------------------------------------------------------
__global__ __launch_bounds__(256) void preconvert_kernel(const float* __restrict__ Q,
                                                         const float* __restrict__ K,
                                                         const float* __restrict__ V) {
    const size_t t = (size_t)blockIdx.x * 256 + threadIdx.x;
    const int which = blockIdx.y;
    const float* src = (which == 0) ? Q : (which == 1) ? K : V;
    float4 v = reinterpret_cast<const float4*>(src)[t];
    if (which == 0) { v.x *= SCALE_LOG2E; v.y *= SCALE_LOG2E; v.z *= SCALE_LOG2E; v.w *= SCALE_LOG2E; }

    __half h0 = __float2half_rn(v.x), h1 = __float2half_rn(v.y);
    __half h2 = __float2half_rn(v.z), h3 = __float2half_rn(v.w);
    uint2 hh{packh2(h0, h1), packh2(h2, h3)};
    if (which == 2) { reinterpret_cast<uint2*>(g_Vhi)[t] = hh; return; }

    __half l0 = __float2half_rn(v.x - __half2float(h0));
    __half l1 = __float2half_rn(v.y - __half2float(h1));
    __half l2 = __float2half_rn(v.z - __half2float(h2));
    __half l3 = __float2half_rn(v.w - __half2float(h3));
    uint2 ll{packh2(l0, l1), packh2(l2, l3)};
    if (which == 0) {
        reinterpret_cast<uint2*>(g_Qhi)[t] = hh;
        reinterpret_cast<uint2*>(g_Qlo)[t] = ll;
    } else {
        reinterpret_cast<uint2*>(g_Khi)[t] = hh;
        reinterpret_cast<uint2*>(g_Klo)[t] = ll;
    }
}

// ---------------------------------------------------------------------------
// Fused attention kernel.
// CTA: 64 q-rows x full LK, 256 threads, 8 warps: wm = wid&3 (16 q-rows),
// wn = wid>>2 (16-wide k-slice of each 32-k chunk).
// Q hi/lo resident in smem (reloaded per k-step). K/V chunks double-buffered.
// ---------------------------------------------------------------------------
static constexpr int RSB    = 272;                // padded row stride (bytes)
static constexpr int OFF_Q  = 0;                  // Qhi 64 rows, then Qlo
static constexpr int QT     = 64 * RSB;           // 17408
static constexpr int OFF_ST = 2 * QT;             // 34816: stages
static constexpr int KSZ    = 32 * RSB;           // 8704
static constexpr int S_KHI = 0, S_KLO = KSZ, S_VHI = 2 * KSZ;
static constexpr int STAGE  = 3 * KSZ;            // 26112
static constexpr int OFF_INV = OFF_ST + 2 * STAGE;  // 87040
static constexpr int SMEM_BYTES = OFF_INV + 1024;   // partial[64] + inv[64] + pad

__global__ __launch_bounds__(256, 2) void fused_attn_kernel(float* __restrict__ P,
                                                            float* __restrict__ R) {
    extern __shared__ char sm[];
    const uint32_t sb = smem_u32(sm);

    const int tid = threadIdx.x, lane = tid & 31, wid = tid >> 5;
    const int wm = wid & 3, wn = wid >> 2;
    const int g = lane >> 2, c2 = (lane & 3) * 2;
    const int qt = blockIdx.x * 64, b = blockIdx.y;

    // ---- stage Q (hi/lo) ----
    {
        const size_t qbase = ((size_t)b * LQ + qt) * DIM;
#pragma unroll
        for (int it = 0; it < 4; ++it) {
            int i = tid + it * 256;               // 0..1023
            int row = i >> 4, chk = i & 15;
            uint32_t so = (uint32_t)(row * RSB + chk * 16);
            const size_t gg = qbase + (size_t)row * DIM + chk * 8;
            cp16(sb + OFF_Q + so,      g_Qhi + gg);
            cp16(sb + OFF_Q + QT + so, g_Qlo + gg);
        }
    }
    // ---- stage chunk 0 ----
    {
        const size_t kb = (size_t)b * LK * DIM;
#pragma unroll
        for (int it = 0; it < 2; ++it) {
            int i = tid + it * 256;               // 0..511
            int row = i >> 4, chk = i & 15;
            uint32_t so = (uint32_t)(row * RSB + chk * 16);
            const size_t gg = kb + (size_t)row * DIM + chk * 8;
            cp16(sb + OFF_ST + S_KHI + so, g_Khi + gg);
            cp16(sb + OFF_ST + S_KLO + so, g_Klo + gg);
            cp16(sb + OFF_ST + S_VHI + so, g_Vhi + gg);
        }
    }
    cp_commit(); cp_wait0();
    __syncthreads();

    // lane offset components (layouts verified in prior rounds)
    const uint32_t aoff  = (uint32_t)((lane & 15) * RSB + (lane >> 4) * 16);
    const uint32_t boff  = (uint32_t)(((lane & 7) + (lane >> 4) * 8) * RSB + ((lane >> 3) & 1) * 16);
    const uint32_t boffT = (uint32_t)(((lane & 7) + ((lane >> 3) & 1) * 8) * RSB + (lane >> 4) * 16);

    const uint32_t qaHi = sb + OFF_Q +      (uint32_t)(wm * 16) * RSB + aoff;
    const uint32_t qaLo = sb + OFF_Q + QT + (uint32_t)(wm * 16) * RSB + aoff;

    float racc[16][4];
#pragma unroll
    for (int j = 0; j < 16; ++j)
#pragma unroll
        for (int c = 0; c < 4; ++c) racc[j][c] = 0.f;
    float rs0 = 0.f, rs1 = 0.f;

    // E pointers: this thread covers rows (qt+wm*16+g, +8), cols kc*32 + wn*16 + ...
    float* Er0 = P + ((size_t)b * LQ + qt + wm * 16 + g) * LK + wn * 16 + c2;
    float* Er1 = Er0 + (size_t)8 * LK;

#pragma unroll 1
    for (int kc = 0; kc < 64; ++kc) {
        if (kc < 63) {
            const uint32_t dst = sb + OFF_ST + (uint32_t)(((kc + 1) & 1) * STAGE);
            const size_t kb = ((size_t)b * LK + (kc + 1) * 32) * DIM;
#pragma unroll
            for (int it = 0; it < 2; ++it) {
                int i = tid + it * 256;
                int row = i >> 4, chk = i & 15;
                uint32_t so = (uint32_t)(row * RSB + chk * 16);
                const size_t gg = kb + (size_t)row * DIM + chk * 8;
                cp16(dst + S_KHI + so, g_Khi + gg);
                cp16(dst + S_KLO + so, g_Klo + gg);
                cp16(dst + S_VHI + so, g_Vhi + gg);
            }
            cp_commit();
        }

        const uint32_t buf = sb + OFF_ST + (uint32_t)((kc & 1) * STAGE);

        // ---- QK: warp computes S[16q x 16k] (its wn k-slice), 3 products ----
        float s[2][4];
#pragma unroll
        for (int j = 0; j < 2; ++j)
#pragma unroll
            for (int c = 0; c < 4; ++c) s[j][c] = 0.f;

        const uint32_t kh = buf + S_KHI + (uint32_t)(wn * 16) * RSB + boff;
        const uint32_t kl = buf + S_KLO + (uint32_t)(wn * 16) * RSB + boff;
#pragma unroll
        for (int ks = 0; ks < 8; ++ks) {
            uint32_t qh[4], ql[4], bh[4], bl[4];
            ldsm4(qh, qaHi + ks * 32);
            ldsm4(ql, qaLo + ks * 32);
            ldsm4(bh, kh + ks * 32);
            ldsm4(bl, kl + ks * 32);
            mma16816(s[0], qh, bh[0], bh[1]);
            mma16816(s[1], qh, bh[2], bh[3]);
            mma16816(s[0], ql, bh[0], bh[1]);
            mma16816(s[1], ql, bh[2], bh[3]);
            mma16816(s[0], qh, bl[0], bl[1]);
            mma16816(s[1], qh, bl[2], bl[3]);
        }

        // ---- exp2 -> store unnormalized E, rowsums, pack A-frags ----
        float e[2][4];
#pragma unroll
        for (int j = 0; j < 2; ++j) {
            e[j][0] = ex2(s[j][0]); e[j][1] = ex2(s[j][1]);
            e[j][2] = ex2(s[j][2]); e[j][3] = ex2(s[j][3]);
            rs0 += e[j][0] + e[j][1];
            rs1 += e[j][2] + e[j][3];
            float2 v0{e[j][0], e[j][1]}, v1{e[j][2], e[j][3]};
            *reinterpret_cast<float2*>(Er0 + kc * 32 + j * 8) = v0;
            *reinterpret_cast<float2*>(Er1 + kc * 32 + j * 8) = v1;
        }
        uint32_t sh[4], sl[4];
#pragma unroll
        for (int j = 0; j < 2; ++j) {
            __half h0 = __float2half_rn(e[j][0]), h1 = __float2half_rn(e[j][1]);
            __half h2 = __float2half_rn(e[j][2]), h3 = __float2half_rn(e[j][3]);
            sh[j * 2 + 0] = packh2(h0, h1);
            sh[j * 2 + 1] = packh2(h2, h3);
            sl[j * 2 + 0] = packh2(__float2half_rn(e[j][0] - __half2float(h0)),
                                   __float2half_rn(e[j][1] - __half2float(h1)));
            sl[j * 2 + 1] = packh2(__float2half_rn(e[j][2] - __half2float(h2)),
                                   __float2half_rn(e[j][3] - __half2float(h3)));
        }

        // ---- PV: racc += (Shi + Slo) * Vhi over this warp's k16 slice ----
        const uint32_t vb = buf + S_VHI + (uint32_t)(wn * 16) * RSB + boffT;
#pragma unroll
        for (int nb = 0; nb < 8; ++nb) {
            uint32_t bv[4];
            ldsm4t(bv, vb + nb * 32);
            mma16816(racc[nb * 2],     sh, bv[0], bv[1]);
            mma16816(racc[nb * 2],     sl, bv[0], bv[1]);
            mma16816(racc[nb * 2 + 1], sh, bv[2], bv[3]);
            mma16816(racc[nb * 2 + 1], sl, bv[2], bv[3]);
        }

        cp_wait0();
        __syncthreads();
    }

    // ---- cross-warp combine (wn pairs), rowsums, R store ----
    rs0 += __shfl_xor_sync(0xFFFFFFFFu, rs0, 1);
    rs0 += __shfl_xor_sync(0xFFFFFFFFu, rs0, 2);
    rs1 += __shfl_xor_sync(0xFFFFFFFFu, rs1, 1);
    rs1 += __shfl_xor_sync(0xFFFFFFFFu, rs1, 2);

    float* partial = reinterpret_cast<float*>(sm + OFF_INV);        // 64 floats
    float* inv     = reinterpret_cast<float*>(sm + OFF_INV + 256);  // 64 floats

    __syncthreads();   // stages + Q dead; reduce area = sm[0..32KB)

    if (wn == 1) {
        // dump racc + rowsum partials
        float4* red = reinterpret_cast<float4*>(sm + wm * 8192);
#pragma unroll
        for (int j = 0; j < 16; ++j)
            red[j * 32 + lane] = *reinterpret_cast<float4*>(racc[j]);
        if ((lane & 3) == 0) {
            partial[wm * 16 + g]     = rs0;
            partial[wm * 16 + 8 + g] = rs1;
        }
    }
    __syncthreads();

    if (wn == 0) {
        const float4* red = reinterpret_cast<const float4*>(sm + wm * 8192);
#pragma unroll
        for (int j = 0; j < 16; ++j) {
            float4 o = red[j * 32 + lane];
            racc[j][0] += o.x; racc[j][1] += o.y; racc[j][2] += o.z; racc[j][3] += o.w;
        }
        const int row0 = wm * 16 + g, row1 = row0 + 8;
        const float iv0 = 1.f / (rs0 + partial[row0]);
        const float iv1 = 1.f / (rs1 + partial[row1]);
        if ((lane & 3) == 0) { inv[row0] = iv0; inv[row1] = iv1; }

        float* Rp = R + ((size_t)b * LQ + qt + row0) * DIM + c2;
#pragma unroll
        for (int j = 0; j < 16; ++j) {
            float2 v0{racc[j][0] * iv0, racc[j][1] * iv0};
            float2 v1{racc[j][2] * iv1, racc[j][3] * iv1};
            *reinterpret_cast<float2*>(Rp + j * 8)           = v0;
            *reinterpret_cast<float2*>(Rp + 8 * DIM + j * 8) = v1;
        }
    }
    __syncthreads();

    // ---- normalize P rows in place (64 rows x 2048) ----
    float* Pt = P + ((size_t)b * LQ + qt) * LK;
#pragma unroll 4
    for (int it = 0; it < 128; ++it) {
        int idx = tid + it * 256;          // 0..32767 float4 slots
        int r = idx >> 9, c4 = idx & 511;
        float4* p = reinterpret_cast<float4*>(Pt + (size_t)r * LK) + c4;
        float4 v = *p;
        const float iv = inv[r];
        v.x *= iv; v.y *= iv; v.z *= iv; v.w *= iv;
        *p = v;
    }
}

// ---------------------------------------------------------------------------
// Launch: d_out = [ R | P ]
// ---------------------------------------------------------------------------
extern "C" void kernel_launch(void* const* d_in, const int* in_sizes, int n_in,
                              void* d_out, int out_size) {
    const float* Q = (const float*)d_in[0];
    const float* K = (const float*)d_in[1];
    const float* V = (const float*)d_in[2];
    float* R = (float*)d_out;
    float* P = (float*)d_out + (size_t)BATCH * LQ * DIM;

    cudaFuncSetAttribute(fused_attn_kernel, cudaFuncAttributeMaxDynamicSharedMemorySize, SMEM_BYTES);

    {
        dim3 grid((unsigned)(NEL / 4 / 256), 3);
        preconvert_kernel<<<grid, 256>>>(Q, K, V);
    }
    {
        dim3 grid(LQ / 64, BATCH);
        fused_attn_kernel<<<grid, 256, SMEM_BYTES>>>(P, R);
    }
}